// round 13
// baseline (speedup 1.0000x reference)
#include <cuda_runtime.h>
#include <cuda_fp16.h>
#include <cuda.h>
#include <cstdint>

using u32 = uint32_t;

// ---------------- problem dims ----------------
constexpr int Mdim = 8192, Ndim = 4096, KL = 512, RANKS = 8;
constexpr int K4 = RANKS * KL;                 // 4096: plain fp16, 1:1 K packing

// ---------------- GEMM tiling ----------------
constexpr int BM = 128;                        // M per CTA
constexpr int BN = 128;                        // N per CTA
constexpr int BKB = 64;                        // fp16 k per SMEM stage (128B rows)
constexpr int NT = K4 / BKB;                   // 64 k-tiles
constexpr int THREADS = 256;                   // 8 warps: 2(m) x 4(n), warp 64x32

constexpr int A_BYTES = BM * 128;              // 16 KB
constexpr int B_BYTES = BN * 128;              // 16 KB
constexpr int STAGE_BYTES = A_BYTES + B_BYTES; // 32 KB
constexpr int STAGES = 3;
constexpr int CTRL = STAGES * STAGE_BYTES;     // 98304
constexpr int SMEM_TOTAL = CTRL + 64;          // + 6 mbarriers -> 2 CTAs/SM

// ---------------- scratch (device globals = sanctioned scratch) ----------------
__device__ __half g_A2[(size_t)Mdim * K4];   // 67 MB : fl16(a)
__device__ __half g_B2[(size_t)Ndim * K4];   // 33 MB : fl16(b)

// ---------------- PTX helpers ----------------
__device__ __forceinline__ u32 smem_u32(const void* p) {
    u32 r;
    asm("{ .reg .u64 t; cvta.to.shared.u64 t, %1; cvt.u32.u64 %0, t; }"
        : "=r"(r) : "l"(p));
    return r;
}

__device__ __forceinline__ void mbar_init(u32 addr, u32 cnt) {
    asm volatile("mbarrier.init.shared.b64 [%0], %1;" :: "r"(addr), "r"(cnt) : "memory");
}
__device__ __forceinline__ void mbar_expect_tx(u32 addr, u32 bytes) {
    asm volatile("mbarrier.arrive.expect_tx.shared.b64 _, [%0], %1;"
                 :: "r"(addr), "r"(bytes) : "memory");
}
__device__ __forceinline__ void mbar_arrive(u32 addr) {
    asm volatile("mbarrier.arrive.shared.b64 _, [%0];" :: "r"(addr) : "memory");
}
__device__ __forceinline__ void mbar_wait(u32 addr, u32 parity) {
    asm volatile(
        "{\n\t.reg .pred P;\n"
        "WL%=:\n\t"
        "mbarrier.try_wait.parity.acquire.cta.shared::cta.b64 P, [%0], %1, 0x989680;\n\t"
        "@P bra WD%=;\n\t"
        "bra WL%=;\n"
        "WD%=:\n\t}"
        :: "r"(addr), "r"(parity) : "memory");
}

__device__ __forceinline__ void tma2d(u32 smem, const void* tmap, int x, int y, u32 mbar) {
    asm volatile(
        "cp.async.bulk.tensor.2d.shared::cta.global.tile.mbarrier::complete_tx::bytes "
        "[%0], [%1, {%2, %3}], [%4];"
        :: "r"(smem), "l"(tmap), "r"(x), "r"(y), "r"(mbar) : "memory");
}

__device__ __forceinline__ void ldsm_x4(u32& r0, u32& r1, u32& r2, u32& r3, u32 a) {
    asm volatile("ldmatrix.sync.aligned.m8n8.x4.shared.b16 {%0,%1,%2,%3}, [%4];"
                 : "=r"(r0), "=r"(r1), "=r"(r2), "=r"(r3) : "r"(a));
}
__device__ __forceinline__ void hmma_f16(float* c, const u32* a, u32 b0, u32 b1) {
    asm volatile(
        "mma.sync.aligned.m16n8k16.row.col.f32.f16.f16.f32 "
        "{%0,%1,%2,%3}, {%4,%5,%6,%7}, {%8,%9}, {%0,%1,%2,%3};"
        : "+f"(c[0]), "+f"(c[1]), "+f"(c[2]), "+f"(c[3])
        : "r"(a[0]), "r"(a[1]), "r"(a[2]), "r"(a[3]), "r"(b0), "r"(b1));
}

// ---------------- conversion: fp32 -> fp16 (1:1) ----------------
__global__ void __launch_bounds__(256)
convert_kernel(const float* __restrict__ a, const float* __restrict__ b)
{
    constexpr size_t ACH = (size_t)RANKS * Mdim * KL / 8;   // 4,194,304
    constexpr size_t BCH = (size_t)RANKS * Ndim * KL / 8;   // 2,097,152
    size_t id = (size_t)blockIdx.x * 256 + threadIdx.x;
    if (id >= ACH + BCH) return;

    bool isA = id < ACH;
    size_t cid = isA ? id : id - ACH;

    size_t src_row = cid >> 6;            // 64 chunks of 8 floats per (src,row)
    int k0 = (int)(cid & 63) * 8;
    int srk, row;
    if (isA) { srk = (int)(src_row / Mdim); row = (int)(src_row % Mdim); }
    else     { srk = (int)(src_row / Ndim); row = (int)(src_row % Ndim); }

    const float* src = (isA ? a : b) + cid * 8;
    __half* dst = (isA ? g_A2 : g_B2)
        + (size_t)row * K4 + (size_t)(srk * KL + k0);

    float4 f0 = ((const float4*)src)[0];
    float4 f1 = ((const float4*)src)[1];
    float xs[8] = {f0.x, f0.y, f0.z, f0.w, f1.x, f1.y, f1.z, f1.w};

    __align__(16) __half ov[8];
#pragma unroll
    for (int i = 0; i < 8; i++) ov[i] = __float2half_rn(xs[i]);
    *(uint4*)dst = *(const uint4*)ov;
}

// ---------------- HMMA GEMM with TMA + mbarrier pipeline ----------------
__global__ void __launch_bounds__(THREADS, 2)
gemm_mma_kernel(const __grid_constant__ CUtensorMap tmA,
                const __grid_constant__ CUtensorMap tmB,
                float* __restrict__ C)
{
    extern __shared__ __align__(1024) char smem[];
    const u32 sbase = smem_u32(smem);
    const int tid = threadIdx.x;
    const int lane = tid & 31;
    const int w = tid >> 5;            // 8 warps
    const int wm = w >> 2;             // 0..1 : warp row (64 M each)
    const int wn = w & 3;              // 0..3 : warp col (32 N each)

    const int m0 = blockIdx.y * BM;
    const int n0 = blockIdx.x * BN;

    const u32 mb_full = sbase + CTRL;          // 3 x u64
    const u32 mb_empty = sbase + CTRL + 24;    // 3 x u64

    if (tid == 0) {
#pragma unroll
        for (int s = 0; s < 3; s++) {
            mbar_init(mb_full + s * 8, 1);
            mbar_init(mb_empty + s * 8, 8);    // one arrive per warp
        }
    }
    __syncthreads();
    asm volatile("fence.proxy.async.shared::cta;" ::: "memory");

    // ---- prologue: TMA tiles 0,1 into stages 0,1 ----
    if (tid == 0) {
#pragma unroll
        for (int p = 0; p < 2; p++) {
            mbar_expect_tx(mb_full + p * 8, STAGE_BYTES);
            tma2d(sbase + p * STAGE_BYTES,           &tmA, p * BKB, m0, mb_full + p * 8);
            tma2d(sbase + p * STAGE_BYTES + A_BYTES, &tmB, p * BKB, n0, mb_full + p * 8);
        }
    }

    // ---- ldmatrix address precomputation with XOR-folded swizzle ----
    // addr(frag, ks) = base(frag) ^ (ks*32); valid since base ≡ fx2 (mod 128)
    // and kb+khalf == kb^khalf (bit-disjoint).
    const u32 frag_xor = (u32)(lane & 7) * 16;
    const u32 khalf = (u32)((lane >> 4) & 1) * 16;
    const u32 fx2 = khalf ^ frag_xor;                    // low 7 bits
    const int frag_row = (((lane >> 3) & 1) << 3) + (lane & 7);
    u32 pA[4];
#pragma unroll
    for (int mb = 0; mb < 4; mb++)
        pA[mb] = (u32)(wm * 64 + mb * 16 + frag_row) * 128 + fx2;
    u32 pB[2];
#pragma unroll
    for (int nb = 0; nb < 2; nb++)
        pB[nb] = (u32)(wn * 32 + nb * 16 + frag_row) * 128 + fx2 + A_BYTES;

    float acc[4][4][4];
#pragma unroll
    for (int i = 0; i < 4; i++)
#pragma unroll
        for (int j = 0; j < 4; j++)
#pragma unroll
            for (int q = 0; q < 4; q++) acc[i][j][q] = 0.f;

    u32 af[2][4][4];
    u32 bf[2][2][4];
    u32 tA0, tA1, tA2, tA3, tB0, tB1;     // per-tile fragment bases

#define SET_BASES(SB)                                                        \
    { tA0 = (SB) + pA[0]; tA1 = (SB) + pA[1]; tA2 = (SB) + pA[2];            \
      tA3 = (SB) + pA[3]; tB0 = (SB) + pB[0]; tB1 = (SB) + pB[1]; }

#define LDSM_ALL(buf, kb)                                                    \
    { ldsm_x4(af[buf][0][0], af[buf][0][1], af[buf][0][2], af[buf][0][3],    \
              tA0 ^ (kb));                                                   \
      ldsm_x4(af[buf][1][0], af[buf][1][1], af[buf][1][2], af[buf][1][3],    \
              tA1 ^ (kb));                                                   \
      ldsm_x4(af[buf][2][0], af[buf][2][1], af[buf][2][2], af[buf][2][3],    \
              tA2 ^ (kb));                                                   \
      ldsm_x4(af[buf][3][0], af[buf][3][1], af[buf][3][2], af[buf][3][3],    \
              tA3 ^ (kb));                                                   \
      ldsm_x4(bf[buf][0][0], bf[buf][0][1], bf[buf][0][2], bf[buf][0][3],    \
              tB0 ^ (kb));                                                   \
      ldsm_x4(bf[buf][1][0], bf[buf][1][1], bf[buf][1][2], bf[buf][1][3],    \
              tB1 ^ (kb)); }

#define HMMA_ALL(buf)                                                        \
    _Pragma("unroll")                                                        \
    for (int mb = 0; mb < 4; mb++) {                                         \
        hmma_f16(acc[mb][0], af[buf][mb], bf[buf][0][0], bf[buf][0][2]);     \
        hmma_f16(acc[mb][1], af[buf][mb], bf[buf][0][1], bf[buf][0][3]);     \
        hmma_f16(acc[mb][2], af[buf][mb], bf[buf][1][0], bf[buf][1][2]);     \
        hmma_f16(acc[mb][3], af[buf][mb], bf[buf][1][1], bf[buf][1][3]);     \
    }

    // ---- steady-state entry: tile 0 ks0 fragments resident before the loop ----
    mbar_wait(mb_full + 0, 0);
    SET_BASES(sbase);
    LDSM_ALL(0, 0);

    // ---- main loop (rolled, as R11) ----
    int stage = 0, fpar = 0, epar = 0;
    for (int t = 0; t < NT; t++) {
        int s2 = stage + 2; if (s2 >= 3) s2 -= 3;
        if (t + 2 < NT) {
            if (tid == 0) {
                if (t + 2 >= 3) mbar_wait(mb_empty + s2 * 8, (u32)epar);
                mbar_expect_tx(mb_full + s2 * 8, STAGE_BYTES);
                tma2d(sbase + s2 * STAGE_BYTES,           &tmA, (t + 2) * BKB, m0,
                      mb_full + s2 * 8);
                tma2d(sbase + s2 * STAGE_BYTES + A_BYTES, &tmB, (t + 2) * BKB, n0,
                      mb_full + s2 * 8);
            }
            if (t + 2 >= 3 && s2 == 2) epar ^= 1;
        }

        SET_BASES(sbase + stage * STAGE_BYTES);   // current-tile bases (6 IADD)

        LDSM_ALL(1, 32);   HMMA_ALL(0);           // ks1 frags | ks0 HMMA
        LDSM_ALL(0, 64);   HMMA_ALL(1);           // ks2 frags | ks1 HMMA
        LDSM_ALL(1, 96);                          // ks3 frags (last stage read)

        // release the stage as early as possible (one arrive per warp)
        __syncwarp();
        if (lane == 0) mbar_arrive(mb_empty + stage * 8);

        HMMA_ALL(0);                              // ks2 HMMAs
        HMMA_ALL(1);                              // ks3 HMMAs queued

        if (t + 1 < NT) {          // overlap next-tile wait+ldsm with ks2/3 drain
            int ns = stage + 1; if (ns >= 3) ns -= 3;
            const u32 npar = (stage == 2) ? (u32)(fpar ^ 1) : (u32)fpar;
            mbar_wait(mb_full + ns * 8, npar);
            SET_BASES(sbase + ns * STAGE_BYTES);
            LDSM_ALL(0, 0);                       // next tile ks0 -> buf 0
        }

        if (++stage == 3) { stage = 0; fpar ^= 1; }
    }

    // ---- epilogue ----
    const int er = lane >> 2;
    const int ec = (lane & 3) * 2;
#pragma unroll
    for (int mb = 0; mb < 4; mb++) {
#pragma unroll
        for (int nb = 0; nb < 4; nb++) {
            float* base = C + (size_t)(m0 + wm * 64 + mb * 16 + er) * Ndim
                            + (n0 + wn * 32 + nb * 8 + ec);
            *(float2*)base = make_float2(acc[mb][nb][0], acc[mb][nb][1]);
            *(float2*)(base + (size_t)8 * Ndim) = make_float2(acc[mb][nb][2], acc[mb][nb][3]);
        }
    }
}

// ---------------- launch ----------------
typedef CUresult (*tmap_encode_fn)(
    CUtensorMap*, CUtensorMapDataType, cuuint32_t, void*,
    const cuuint64_t*, const cuuint64_t*, const cuuint32_t*, const cuuint32_t*,
    CUtensorMapInterleave, CUtensorMapSwizzle, CUtensorMapL2promotion,
    CUtensorMapFloatOOBfill);

extern "C" void kernel_launch(void* const* d_in, const int* in_sizes, int n_in,
                              void* d_out, int out_size)
{
    const float* a = (const float*)d_in[0];   // [8, 8192, 512] fp32
    const float* b = (const float*)d_in[1];   // [8, 4096, 512] fp32
    float* c = (float*)d_out;                 // [8192, 4096] fp32

    constexpr size_t TOTAL_CHUNKS =
        ((size_t)RANKS * Mdim * KL + (size_t)RANKS * Ndim * KL) / 8;  // 6,291,456
    convert_kernel<<<(unsigned)(TOTAL_CHUNKS / 256), 256>>>(a, b);

    // Build tensormaps (host-side, deterministic, no allocation)
    void* pa = nullptr; void* pb = nullptr;
    cudaGetSymbolAddress(&pa, g_A2);
    cudaGetSymbolAddress(&pb, g_B2);

    void* fn = nullptr;
    cudaDriverEntryPointQueryResult qr;
    cudaGetDriverEntryPointByVersion("cuTensorMapEncodeTiled", &fn, 12000,
                                     cudaEnableDefault, &qr);
    tmap_encode_fn enc = (tmap_encode_fn)fn;

    CUtensorMap tA, tB;
    cuuint64_t dimsA[2] = {(cuuint64_t)K4, (cuuint64_t)Mdim};
    cuuint64_t dimsB[2] = {(cuuint64_t)K4, (cuuint64_t)Ndim};
    cuuint64_t strides[1] = {(cuuint64_t)K4 * 2};
    cuuint32_t box[2] = {(cuuint32_t)BKB, (cuuint32_t)BM};   // 64 x 128 (=128B x 128 rows)
    cuuint32_t es[2] = {1, 1};
    enc(&tA, CU_TENSOR_MAP_DATA_TYPE_FLOAT16, 2, pa, dimsA, strides, box, es,
        CU_TENSOR_MAP_INTERLEAVE_NONE, CU_TENSOR_MAP_SWIZZLE_128B,
        CU_TENSOR_MAP_L2_PROMOTION_L2_128B, CU_TENSOR_MAP_FLOAT_OOB_FILL_NONE);
    enc(&tB, CU_TENSOR_MAP_DATA_TYPE_FLOAT16, 2, pb, dimsB, strides, box, es,
        CU_TENSOR_MAP_INTERLEAVE_NONE, CU_TENSOR_MAP_SWIZZLE_128B,
        CU_TENSOR_MAP_L2_PROMOTION_L2_128B, CU_TENSOR_MAP_FLOAT_OOB_FILL_NONE);

    cudaFuncSetAttribute(gemm_mma_kernel,
                         cudaFuncAttributeMaxDynamicSharedMemorySize, SMEM_TOTAL);
    dim3 grid(Ndim / BN, Mdim / BM);          // (32, 64) = 2048 CTAs, 2 per SM
    gemm_mma_kernel<<<grid, THREADS, SMEM_TOTAL>>>(tA, tB, c);
}

// round 14
// speedup vs baseline: 1.0210x; 1.0210x over previous
#include <cuda_runtime.h>
#include <cuda_fp16.h>
#include <cuda.h>
#include <cstdint>

using u32 = uint32_t;

// ---------------- problem dims ----------------
constexpr int Mdim = 8192, Ndim = 4096, KL = 512, RANKS = 8;
constexpr int K4 = RANKS * KL;                 // 4096: plain fp16, 1:1 K packing

// ---------------- GEMM tiling ----------------
constexpr int BM = 128;                        // M per CTA
constexpr int BN = 128;                        // N per CTA
constexpr int BKB = 64;                        // fp16 k per SMEM stage (128B rows)
constexpr int NT = K4 / BKB;                   // 64 k-tiles
constexpr int THREADS = 256;                   // 8 warps: 2(m) x 4(n), warp 64x32

constexpr int A_BYTES = BM * 128;              // 16 KB
constexpr int B_BYTES = BN * 128;              // 16 KB
constexpr int STAGE_BYTES = A_BYTES + B_BYTES; // 32 KB
constexpr int STAGES = 3;
constexpr int CTRL = STAGES * STAGE_BYTES;     // 98304
constexpr int SMEM_TOTAL = CTRL + 64;          // + 6 mbarriers -> 2 CTAs/SM

// ---------------- scratch (device globals = sanctioned scratch) ----------------
__device__ __half g_A2[(size_t)Mdim * K4];   // 67 MB : fl16(a)
__device__ __half g_B2[(size_t)Ndim * K4];   // 33 MB : fl16(b)

// ---------------- PTX helpers ----------------
__device__ __forceinline__ u32 smem_u32(const void* p) {
    u32 r;
    asm("{ .reg .u64 t; cvta.to.shared.u64 t, %1; cvt.u32.u64 %0, t; }"
        : "=r"(r) : "l"(p));
    return r;
}

__device__ __forceinline__ void mbar_init(u32 addr, u32 cnt) {
    asm volatile("mbarrier.init.shared.b64 [%0], %1;" :: "r"(addr), "r"(cnt) : "memory");
}
__device__ __forceinline__ void mbar_expect_tx(u32 addr, u32 bytes) {
    asm volatile("mbarrier.arrive.expect_tx.shared.b64 _, [%0], %1;"
                 :: "r"(addr), "r"(bytes) : "memory");
}
__device__ __forceinline__ void mbar_arrive(u32 addr) {
    asm volatile("mbarrier.arrive.shared.b64 _, [%0];" :: "r"(addr) : "memory");
}
__device__ __forceinline__ void mbar_wait(u32 addr, u32 parity) {
    asm volatile(
        "{\n\t.reg .pred P;\n"
        "WL%=:\n\t"
        "mbarrier.try_wait.parity.acquire.cta.shared::cta.b64 P, [%0], %1, 0x989680;\n\t"
        "@P bra WD%=;\n\t"
        "bra WL%=;\n"
        "WD%=:\n\t}"
        :: "r"(addr), "r"(parity) : "memory");
}

__device__ __forceinline__ void tma2d(u32 smem, const void* tmap, int x, int y, u32 mbar) {
    asm volatile(
        "cp.async.bulk.tensor.2d.shared::cta.global.tile.mbarrier::complete_tx::bytes "
        "[%0], [%1, {%2, %3}], [%4];"
        :: "r"(smem), "l"(tmap), "r"(x), "r"(y), "r"(mbar) : "memory");
}

__device__ __forceinline__ void ldsm_x4(u32& r0, u32& r1, u32& r2, u32& r3, u32 a) {
    asm volatile("ldmatrix.sync.aligned.m8n8.x4.shared.b16 {%0,%1,%2,%3}, [%4];"
                 : "=r"(r0), "=r"(r1), "=r"(r2), "=r"(r3) : "r"(a));
}
__device__ __forceinline__ void hmma_f16(float* c, const u32* a, u32 b0, u32 b1) {
    asm volatile(
        "mma.sync.aligned.m16n8k16.row.col.f32.f16.f16.f32 "
        "{%0,%1,%2,%3}, {%4,%5,%6,%7}, {%8,%9}, {%0,%1,%2,%3};"
        : "+f"(c[0]), "+f"(c[1]), "+f"(c[2]), "+f"(c[3])
        : "r"(a[0]), "r"(a[1]), "r"(a[2]), "r"(a[3]), "r"(b0), "r"(b1));
}

// ---------------- conversion: fp32 -> fp16 (1:1) ----------------
__global__ void __launch_bounds__(256)
convert_kernel(const float* __restrict__ a, const float* __restrict__ b)
{
    constexpr size_t ACH = (size_t)RANKS * Mdim * KL / 8;   // 4,194,304
    constexpr size_t BCH = (size_t)RANKS * Ndim * KL / 8;   // 2,097,152
    size_t id = (size_t)blockIdx.x * 256 + threadIdx.x;
    if (id >= ACH + BCH) return;

    bool isA = id < ACH;
    size_t cid = isA ? id : id - ACH;

    size_t src_row = cid >> 6;            // 64 chunks of 8 floats per (src,row)
    int k0 = (int)(cid & 63) * 8;
    int srk, row;
    if (isA) { srk = (int)(src_row / Mdim); row = (int)(src_row % Mdim); }
    else     { srk = (int)(src_row / Ndim); row = (int)(src_row % Ndim); }

    const float* src = (isA ? a : b) + cid * 8;
    __half* dst = (isA ? g_A2 : g_B2)
        + (size_t)row * K4 + (size_t)(srk * KL + k0);

    float4 f0 = ((const float4*)src)[0];
    float4 f1 = ((const float4*)src)[1];
    float xs[8] = {f0.x, f0.y, f0.z, f0.w, f1.x, f1.y, f1.z, f1.w};

    __align__(16) __half ov[8];
#pragma unroll
    for (int i = 0; i < 8; i++) ov[i] = __float2half_rn(xs[i]);
    *(uint4*)dst = *(const uint4*)ov;
}

// ---------------- HMMA GEMM with TMA + mbarrier pipeline ----------------
__global__ void __launch_bounds__(THREADS, 2)
gemm_mma_kernel(const __grid_constant__ CUtensorMap tmA,
                const __grid_constant__ CUtensorMap tmB,
                float* __restrict__ C)
{
    extern __shared__ __align__(1024) char smem[];
    const u32 sbase = smem_u32(smem);
    const int tid = threadIdx.x;
    const int lane = tid & 31;
    const int w = tid >> 5;            // 8 warps
    const int wm = w >> 2;             // 0..1 : warp row (64 M each)
    const int wn = w & 3;              // 0..3 : warp col (32 N each)

    const int m0 = blockIdx.y * BM;
    const int n0 = blockIdx.x * BN;

    const u32 mb_full = sbase + CTRL;          // 3 x u64
    const u32 mb_empty = sbase + CTRL + 24;    // 3 x u64

    if (tid == 0) {
#pragma unroll
        for (int s = 0; s < 3; s++) {
            mbar_init(mb_full + s * 8, 1);
            mbar_init(mb_empty + s * 8, 8);    // one arrive per warp
        }
    }
    __syncthreads();
    asm volatile("fence.proxy.async.shared::cta;" ::: "memory");

    // ---- prologue: TMA tiles 0,1 into stages 0,1 ----
    if (tid == 0) {
#pragma unroll
        for (int p = 0; p < 2; p++) {
            mbar_expect_tx(mb_full + p * 8, STAGE_BYTES);
            tma2d(sbase + p * STAGE_BYTES,           &tmA, p * BKB, m0, mb_full + p * 8);
            tma2d(sbase + p * STAGE_BYTES + A_BYTES, &tmB, p * BKB, n0, mb_full + p * 8);
        }
    }

    // ---- ldmatrix address precomputation ----
    const u32 frag_xor = (u32)(lane & 7) * 16;
    const u32 khalf = (u32)((lane >> 4) & 1) * 16;
    const int frag_row = (((lane >> 3) & 1) << 3) + (lane & 7);
    u32 aPre[4];
#pragma unroll
    for (int mb = 0; mb < 4; mb++)
        aPre[mb] = (u32)(wm * 64 + mb * 16 + frag_row) * 128;
    u32 bPre[2];
#pragma unroll
    for (int nb = 0; nb < 2; nb++)
        bPre[nb] = (u32)(wn * 32 + nb * 16 + frag_row) * 128;

    float acc[4][4][4];
#pragma unroll
    for (int i = 0; i < 4; i++)
#pragma unroll
        for (int j = 0; j < 4; j++)
#pragma unroll
            for (int q = 0; q < 4; q++) acc[i][j][q] = 0.f;

    u32 af[2][4][4];
    u32 bf[2][2][4];

    auto ldsm_all = [&](int buf, u32 sA_, u32 sB_, u32 kbyte) {
        const u32 kk = (kbyte + khalf) ^ frag_xor;
#pragma unroll
        for (int mb = 0; mb < 4; mb++)
            ldsm_x4(af[buf][mb][0], af[buf][mb][1], af[buf][mb][2], af[buf][mb][3],
                    sA_ + aPre[mb] + kk);
#pragma unroll
        for (int nb = 0; nb < 2; nb++)
            ldsm_x4(bf[buf][nb][0], bf[buf][nb][1], bf[buf][nb][2], bf[buf][nb][3],
                    sB_ + bPre[nb] + kk);
    };
    auto hmma_all = [&](int buf) {
#pragma unroll
        for (int mb = 0; mb < 4; mb++)
#pragma unroll
            for (int nb = 0; nb < 2; nb++) {
                hmma_f16(acc[mb][2 * nb + 0], af[buf][mb], bf[buf][nb][0], bf[buf][nb][2]);
                hmma_f16(acc[mb][2 * nb + 1], af[buf][mb], bf[buf][nb][1], bf[buf][nb][3]);
            }
    };

    // ---- steady-state entry: tile 0 ks0 fragments resident before the loop ----
    mbar_wait(mb_full + 0, 0);
    ldsm_all(0, sbase, sbase + A_BYTES, 0);

    // ---- main loop ----
    // Tile t body (ks0 frags already in buf0):
    //   ldsm ks1; HMMA ks0 | ldsm ks2; HMMA ks1 | ldsm ks3; HMMA ks2
    //   per-warp arrive empty(stage)
    //   producer: TMA tile t+2        <- moved here: off warp0's tile-top
    //   HMMA ks3 (queued) ; wait full(t+1) ; ldsm(t+1, ks0)
    int stage = 0, fpar = 0, epar = 0;
    for (int t = 0; t < NT; t++) {
        const u32 sA = sbase + stage * STAGE_BYTES;
        const u32 sB = sA + A_BYTES;

        ldsm_all(1, sA, sB, 32);   hmma_all(0);
        ldsm_all(0, sA, sB, 64);   hmma_all(1);
        ldsm_all(1, sA, sB, 96);   hmma_all(0);

        // all reads of this stage are issued; release it (one arrive per warp)
        __syncwarp();
        if (lane == 0) mbar_arrive(mb_empty + stage * 8);

        // producer: issue tile t+2 while this warp's ks2 HMMAs drain
        {
            int s2 = stage + 2; if (s2 >= 3) s2 -= 3;
            if (t + 2 < NT) {
                if (tid == 0) {
                    if (t + 2 >= 3) mbar_wait(mb_empty + s2 * 8, (u32)epar);
                    mbar_expect_tx(mb_full + s2 * 8, STAGE_BYTES);
                    tma2d(sbase + s2 * STAGE_BYTES,           &tmA, (t + 2) * BKB, m0,
                          mb_full + s2 * 8);
                    tma2d(sbase + s2 * STAGE_BYTES + A_BYTES, &tmB, (t + 2) * BKB, n0,
                          mb_full + s2 * 8);
                }
                if (t + 2 >= 3 && s2 == 2) epar ^= 1;
            }
        }

        hmma_all(1);               // ks3 HMMAs queued into the tensor pipe

        if (t + 1 < NT) {          // overlap next-tile wait+ldsm with ks3 drain
            int ns = stage + 1; if (ns >= 3) ns -= 3;
            const u32 npar = (stage == 2) ? (u32)(fpar ^ 1) : (u32)fpar;
            mbar_wait(mb_full + ns * 8, npar);
            const u32 nA = sbase + ns * STAGE_BYTES;
            ldsm_all(0, nA, nA + A_BYTES, 0);
        }

        if (++stage == 3) { stage = 0; fpar ^= 1; }
    }

    // ---- epilogue ----
    const int er = lane >> 2;
    const int ec = (lane & 3) * 2;
#pragma unroll
    for (int mb = 0; mb < 4; mb++) {
#pragma unroll
        for (int nb = 0; nb < 4; nb++) {
            float* base = C + (size_t)(m0 + wm * 64 + mb * 16 + er) * Ndim
                            + (n0 + wn * 32 + nb * 8 + ec);
            *(float2*)base = make_float2(acc[mb][nb][0], acc[mb][nb][1]);
            *(float2*)(base + (size_t)8 * Ndim) = make_float2(acc[mb][nb][2], acc[mb][nb][3]);
        }
    }
}

// ---------------- launch ----------------
typedef CUresult (*tmap_encode_fn)(
    CUtensorMap*, CUtensorMapDataType, cuuint32_t, void*,
    const cuuint64_t*, const cuuint64_t*, const cuuint32_t*, const cuuint32_t*,
    CUtensorMapInterleave, CUtensorMapSwizzle, CUtensorMapL2promotion,
    CUtensorMapFloatOOBfill);

extern "C" void kernel_launch(void* const* d_in, const int* in_sizes, int n_in,
                              void* d_out, int out_size)
{
    const float* a = (const float*)d_in[0];   // [8, 8192, 512] fp32
    const float* b = (const float*)d_in[1];   // [8, 4096, 512] fp32
    float* c = (float*)d_out;                 // [8192, 4096] fp32

    constexpr size_t TOTAL_CHUNKS =
        ((size_t)RANKS * Mdim * KL + (size_t)RANKS * Ndim * KL) / 8;  // 6,291,456
    convert_kernel<<<(unsigned)(TOTAL_CHUNKS / 256), 256>>>(a, b);

    // Build tensormaps (host-side, deterministic, no allocation)
    void* pa = nullptr; void* pb = nullptr;
    cudaGetSymbolAddress(&pa, g_A2);
    cudaGetSymbolAddress(&pb, g_B2);

    void* fn = nullptr;
    cudaDriverEntryPointQueryResult qr;
    cudaGetDriverEntryPointByVersion("cuTensorMapEncodeTiled", &fn, 12000,
                                     cudaEnableDefault, &qr);
    tmap_encode_fn enc = (tmap_encode_fn)fn;

    CUtensorMap tA, tB;
    cuuint64_t dimsA[2] = {(cuuint64_t)K4, (cuuint64_t)Mdim};
    cuuint64_t dimsB[2] = {(cuuint64_t)K4, (cuuint64_t)Ndim};
    cuuint64_t strides[1] = {(cuuint64_t)K4 * 2};
    cuuint32_t box[2] = {(cuuint32_t)BKB, (cuuint32_t)BM};   // 64 x 128 (=128B x 128 rows)
    cuuint32_t es[2] = {1, 1};
    enc(&tA, CU_TENSOR_MAP_DATA_TYPE_FLOAT16, 2, pa, dimsA, strides, box, es,
        CU_TENSOR_MAP_INTERLEAVE_NONE, CU_TENSOR_MAP_SWIZZLE_128B,
        CU_TENSOR_MAP_L2_PROMOTION_L2_128B, CU_TENSOR_MAP_FLOAT_OOB_FILL_NONE);
    enc(&tB, CU_TENSOR_MAP_DATA_TYPE_FLOAT16, 2, pb, dimsB, strides, box, es,
        CU_TENSOR_MAP_INTERLEAVE_NONE, CU_TENSOR_MAP_SWIZZLE_128B,
        CU_TENSOR_MAP_L2_PROMOTION_L2_128B, CU_TENSOR_MAP_FLOAT_OOB_FILL_NONE);

    cudaFuncSetAttribute(gemm_mma_kernel,
                         cudaFuncAttributeMaxDynamicSharedMemorySize, SMEM_TOTAL);
    dim3 grid(Ndim / BN, Mdim / BM);          // (32, 64) = 2048 CTAs, 2 per SM
    gemm_mma_kernel<<<grid, THREADS, SMEM_TOTAL>>>(tA, tB, c);
}

// round 15
// speedup vs baseline: 1.0265x; 1.0054x over previous
#include <cuda_runtime.h>
#include <cuda_fp16.h>
#include <cuda.h>
#include <cstdint>

using u32 = uint32_t;

// ---------------- problem dims ----------------
constexpr int Mdim = 8192, Ndim = 4096, KL = 512, RANKS = 8;
constexpr int K4 = RANKS * KL;                 // 4096: plain fp16, 1:1 K packing

// ---------------- GEMM tiling ----------------
constexpr int BM = 128;                        // M per CTA
constexpr int BN = 128;                        // N per CTA
constexpr int BKB = 64;                        // fp16 k per SMEM stage (128B rows)
constexpr int NT = K4 / BKB;                   // 64 k-tiles
constexpr int THREADS = 256;                   // 8 warps: 2(m) x 4(n), warp 64x32

constexpr int A_BYTES = BM * 128;              // 16 KB
constexpr int B_BYTES = BN * 128;              // 16 KB
constexpr int STAGE_BYTES = A_BYTES + B_BYTES; // 32 KB
constexpr int STAGES = 3;
constexpr int CTRL = STAGES * STAGE_BYTES;     // 98304
constexpr int SMEM_TOTAL = CTRL + 64;          // + 6 mbarriers -> 2 CTAs/SM

// ---------------- scratch (device globals = sanctioned scratch) ----------------
__device__ __half g_A2[(size_t)Mdim * K4];   // 67 MB : fl16(a)
__device__ __half g_B2[(size_t)Ndim * K4];   // 33 MB : fl16(b)

// ---------------- PTX helpers ----------------
__device__ __forceinline__ u32 smem_u32(const void* p) {
    u32 r;
    asm("{ .reg .u64 t; cvta.to.shared.u64 t, %1; cvt.u32.u64 %0, t; }"
        : "=r"(r) : "l"(p));
    return r;
}

__device__ __forceinline__ void mbar_init(u32 addr, u32 cnt) {
    asm volatile("mbarrier.init.shared.b64 [%0], %1;" :: "r"(addr), "r"(cnt) : "memory");
}
__device__ __forceinline__ void mbar_expect_tx(u32 addr, u32 bytes) {
    asm volatile("mbarrier.arrive.expect_tx.shared.b64 _, [%0], %1;"
                 :: "r"(addr), "r"(bytes) : "memory");
}
__device__ __forceinline__ void mbar_arrive(u32 addr) {
    asm volatile("mbarrier.arrive.shared.b64 _, [%0];" :: "r"(addr) : "memory");
}
__device__ __forceinline__ void mbar_wait(u32 addr, u32 parity) {
    asm volatile(
        "{\n\t.reg .pred P;\n"
        "WL%=:\n\t"
        "mbarrier.try_wait.parity.acquire.cta.shared::cta.b64 P, [%0], %1, 0x989680;\n\t"
        "@P bra WD%=;\n\t"
        "bra WL%=;\n"
        "WD%=:\n\t}"
        :: "r"(addr), "r"(parity) : "memory");
}

__device__ __forceinline__ void tma2d(u32 smem, const void* tmap, int x, int y, u32 mbar) {
    asm volatile(
        "cp.async.bulk.tensor.2d.shared::cta.global.tile.mbarrier::complete_tx::bytes "
        "[%0], [%1, {%2, %3}], [%4];"
        :: "r"(smem), "l"(tmap), "r"(x), "r"(y), "r"(mbar) : "memory");
}

__device__ __forceinline__ void ldsm_x4(u32& r0, u32& r1, u32& r2, u32& r3, u32 a) {
    asm volatile("ldmatrix.sync.aligned.m8n8.x4.shared.b16 {%0,%1,%2,%3}, [%4];"
                 : "=r"(r0), "=r"(r1), "=r"(r2), "=r"(r3) : "r"(a));
}
__device__ __forceinline__ void hmma_f16(float* c, const u32* a, u32 b0, u32 b1) {
    asm volatile(
        "mma.sync.aligned.m16n8k16.row.col.f32.f16.f16.f32 "
        "{%0,%1,%2,%3}, {%4,%5,%6,%7}, {%8,%9}, {%0,%1,%2,%3};"
        : "+f"(c[0]), "+f"(c[1]), "+f"(c[2]), "+f"(c[3])
        : "r"(a[0]), "r"(a[1]), "r"(a[2]), "r"(a[3]), "r"(b0), "r"(b1));
}

// ---------------- conversion: fp32 -> fp16 (1:1) ----------------
__global__ void __launch_bounds__(256)
convert_kernel(const float* __restrict__ a, const float* __restrict__ b)
{
    constexpr size_t ACH = (size_t)RANKS * Mdim * KL / 8;   // 4,194,304
    constexpr size_t BCH = (size_t)RANKS * Ndim * KL / 8;   // 2,097,152
    size_t id = (size_t)blockIdx.x * 256 + threadIdx.x;
    if (id >= ACH + BCH) return;

    bool isA = id < ACH;
    size_t cid = isA ? id : id - ACH;

    size_t src_row = cid >> 6;            // 64 chunks of 8 floats per (src,row)
    int k0 = (int)(cid & 63) * 8;
    int srk, row;
    if (isA) { srk = (int)(src_row / Mdim); row = (int)(src_row % Mdim); }
    else     { srk = (int)(src_row / Ndim); row = (int)(src_row % Ndim); }

    const float* src = (isA ? a : b) + cid * 8;
    __half* dst = (isA ? g_A2 : g_B2)
        + (size_t)row * K4 + (size_t)(srk * KL + k0);

    float4 f0 = ((const float4*)src)[0];
    float4 f1 = ((const float4*)src)[1];
    float xs[8] = {f0.x, f0.y, f0.z, f0.w, f1.x, f1.y, f1.z, f1.w};

    __align__(16) __half ov[8];
#pragma unroll
    for (int i = 0; i < 8; i++) ov[i] = __float2half_rn(xs[i]);
    *(uint4*)dst = *(const uint4*)ov;
}

// ---------------- HMMA GEMM with TMA + mbarrier pipeline ----------------
__global__ void __launch_bounds__(THREADS, 2)
gemm_mma_kernel(const __grid_constant__ CUtensorMap tmA,
                const __grid_constant__ CUtensorMap tmB,
                float* __restrict__ C)
{
    extern __shared__ __align__(1024) char smem[];
    const u32 sbase = smem_u32(smem);
    const int tid = threadIdx.x;
    const int lane = tid & 31;
    const int w = tid >> 5;            // 8 warps
    const int wm = w >> 2;             // 0..1 : warp row (64 M each)
    const int wn = w & 3;              // 0..3 : warp col (32 N each)

    const int m0 = blockIdx.y * BM;
    const int n0 = blockIdx.x * BN;

    const u32 mb_full = sbase + CTRL;          // 3 x u64
    const u32 mb_empty = sbase + CTRL + 24;    // 3 x u64

    if (tid == 0) {
#pragma unroll
        for (int s = 0; s < 3; s++) {
            mbar_init(mb_full + s * 8, 1);
            mbar_init(mb_empty + s * 8, 8);    // one arrive per warp
        }
    }
    __syncthreads();
    asm volatile("fence.proxy.async.shared::cta;" ::: "memory");

    // ---- prologue: TMA tiles 0,1 into stages 0,1 ----
    if (tid == 0) {
#pragma unroll
        for (int p = 0; p < 2; p++) {
            mbar_expect_tx(mb_full + p * 8, STAGE_BYTES);
            tma2d(sbase + p * STAGE_BYTES,           &tmA, p * BKB, m0, mb_full + p * 8);
            tma2d(sbase + p * STAGE_BYTES + A_BYTES, &tmB, p * BKB, n0, mb_full + p * 8);
        }
    }

    // ---- ldmatrix address precomputation ----
    const u32 frag_xor = (u32)(lane & 7) * 16;
    const u32 khalf = (u32)((lane >> 4) & 1) * 16;
    const int frag_row = (((lane >> 3) & 1) << 3) + (lane & 7);
    u32 aPre[4];
#pragma unroll
    for (int mb = 0; mb < 4; mb++)
        aPre[mb] = (u32)(wm * 64 + mb * 16 + frag_row) * 128;
    u32 bPre[2];
#pragma unroll
    for (int nb = 0; nb < 2; nb++)
        bPre[nb] = (u32)(wn * 32 + nb * 16 + frag_row) * 128;

    float acc[4][4][4];
#pragma unroll
    for (int i = 0; i < 4; i++)
#pragma unroll
        for (int j = 0; j < 4; j++)
#pragma unroll
            for (int q = 0; q < 4; q++) acc[i][j][q] = 0.f;

    u32 af[2][4][4];
    u32 bf[2][2][4];

    auto ldsm_all = [&](int buf, u32 sA_, u32 sB_, u32 kbyte) {
        const u32 kk = (kbyte + khalf) ^ frag_xor;
#pragma unroll
        for (int mb = 0; mb < 4; mb++)
            ldsm_x4(af[buf][mb][0], af[buf][mb][1], af[buf][mb][2], af[buf][mb][3],
                    sA_ + aPre[mb] + kk);
#pragma unroll
        for (int nb = 0; nb < 2; nb++)
            ldsm_x4(bf[buf][nb][0], bf[buf][nb][1], bf[buf][nb][2], bf[buf][nb][3],
                    sB_ + bPre[nb] + kk);
    };
    auto hmma_all = [&](int buf) {
#pragma unroll
        for (int mb = 0; mb < 4; mb++)
#pragma unroll
            for (int nb = 0; nb < 2; nb++) {
                hmma_f16(acc[mb][2 * nb + 0], af[buf][mb], bf[buf][nb][0], bf[buf][nb][2]);
                hmma_f16(acc[mb][2 * nb + 1], af[buf][mb], bf[buf][nb][1], bf[buf][nb][3]);
            }
    };

    // ---- steady-state entry: tile 0 ks0 fragments resident before the loop ----
    mbar_wait(mb_full + 0, 0);
    ldsm_all(0, sbase, sbase + A_BYTES, 0);

    // ---- main loop (R11 ordering; producer OWNED BY WARP s2, rotating) ----
    int stage = 0, fpar = 0, epar = 0;
    for (int t = 0; t < NT; t++) {
        int s2 = stage + 2; if (s2 >= 3) s2 -= 3;
        if (t + 2 < NT) {
            if (lane == 0 && w == s2) {        // rotate producer: warp s2 owns stage s2
                if (t + 2 >= 3) mbar_wait(mb_empty + s2 * 8, (u32)epar);
                mbar_expect_tx(mb_full + s2 * 8, STAGE_BYTES);
                tma2d(sbase + s2 * STAGE_BYTES,           &tmA, (t + 2) * BKB, m0,
                      mb_full + s2 * 8);
                tma2d(sbase + s2 * STAGE_BYTES + A_BYTES, &tmB, (t + 2) * BKB, n0,
                      mb_full + s2 * 8);
            }
            if (t + 2 >= 3 && s2 == 2) epar ^= 1;
        }

        const u32 sA = sbase + stage * STAGE_BYTES;
        const u32 sB = sA + A_BYTES;

        ldsm_all(1, sA, sB, 32);   hmma_all(0);
        ldsm_all(0, sA, sB, 64);   hmma_all(1);
        ldsm_all(1, sA, sB, 96);   hmma_all(0);

        // all reads of this stage are issued; release it (one arrive per warp)
        __syncwarp();
        if (lane == 0) mbar_arrive(mb_empty + stage * 8);

        hmma_all(1);               // ks3 HMMAs queued into the tensor pipe

        if (t + 1 < NT) {          // overlap next-tile wait+ldsm with ks3 drain
            int ns = stage + 1; if (ns >= 3) ns -= 3;
            const u32 npar = (stage == 2) ? (u32)(fpar ^ 1) : (u32)fpar;
            mbar_wait(mb_full + ns * 8, npar);
            const u32 nA = sbase + ns * STAGE_BYTES;
            ldsm_all(0, nA, nA + A_BYTES, 0);
        }

        if (++stage == 3) { stage = 0; fpar ^= 1; }
    }

    // ---- epilogue ----
    const int er = lane >> 2;
    const int ec = (lane & 3) * 2;
#pragma unroll
    for (int mb = 0; mb < 4; mb++) {
#pragma unroll
        for (int nb = 0; nb < 4; nb++) {
            float* base = C + (size_t)(m0 + wm * 64 + mb * 16 + er) * Ndim
                            + (n0 + wn * 32 + nb * 8 + ec);
            *(float2*)base = make_float2(acc[mb][nb][0], acc[mb][nb][1]);
            *(float2*)(base + (size_t)8 * Ndim) = make_float2(acc[mb][nb][2], acc[mb][nb][3]);
        }
    }
}

// ---------------- launch ----------------
typedef CUresult (*tmap_encode_fn)(
    CUtensorMap*, CUtensorMapDataType, cuuint32_t, void*,
    const cuuint64_t*, const cuuint64_t*, const cuuint32_t*, const cuuint32_t*,
    CUtensorMapInterleave, CUtensorMapSwizzle, CUtensorMapL2promotion,
    CUtensorMapFloatOOBfill);

extern "C" void kernel_launch(void* const* d_in, const int* in_sizes, int n_in,
                              void* d_out, int out_size)
{
    const float* a = (const float*)d_in[0];   // [8, 8192, 512] fp32
    const float* b = (const float*)d_in[1];   // [8, 4096, 512] fp32
    float* c = (float*)d_out;                 // [8192, 4096] fp32

    constexpr size_t TOTAL_CHUNKS =
        ((size_t)RANKS * Mdim * KL + (size_t)RANKS * Ndim * KL) / 8;  // 6,291,456
    convert_kernel<<<(unsigned)(TOTAL_CHUNKS / 256), 256>>>(a, b);

    // Build tensormaps (host-side, deterministic, no allocation)
    void* pa = nullptr; void* pb = nullptr;
    cudaGetSymbolAddress(&pa, g_A2);
    cudaGetSymbolAddress(&pb, g_B2);

    void* fn = nullptr;
    cudaDriverEntryPointQueryResult qr;
    cudaGetDriverEntryPointByVersion("cuTensorMapEncodeTiled", &fn, 12000,
                                     cudaEnableDefault, &qr);
    tmap_encode_fn enc = (tmap_encode_fn)fn;

    CUtensorMap tA, tB;
    cuuint64_t dimsA[2] = {(cuuint64_t)K4, (cuuint64_t)Mdim};
    cuuint64_t dimsB[2] = {(cuuint64_t)K4, (cuuint64_t)Ndim};
    cuuint64_t strides[1] = {(cuuint64_t)K4 * 2};
    cuuint32_t box[2] = {(cuuint32_t)BKB, (cuuint32_t)BM};   // 64 x 128 (=128B x 128 rows)
    cuuint32_t es[2] = {1, 1};
    enc(&tA, CU_TENSOR_MAP_DATA_TYPE_FLOAT16, 2, pa, dimsA, strides, box, es,
        CU_TENSOR_MAP_INTERLEAVE_NONE, CU_TENSOR_MAP_SWIZZLE_128B,
        CU_TENSOR_MAP_L2_PROMOTION_L2_128B, CU_TENSOR_MAP_FLOAT_OOB_FILL_NONE);
    enc(&tB, CU_TENSOR_MAP_DATA_TYPE_FLOAT16, 2, pb, dimsB, strides, box, es,
        CU_TENSOR_MAP_INTERLEAVE_NONE, CU_TENSOR_MAP_SWIZZLE_128B,
        CU_TENSOR_MAP_L2_PROMOTION_L2_128B, CU_TENSOR_MAP_FLOAT_OOB_FILL_NONE);

    cudaFuncSetAttribute(gemm_mma_kernel,
                         cudaFuncAttributeMaxDynamicSharedMemorySize, SMEM_TOTAL);
    dim3 grid(Ndim / BN, Mdim / BM);          // (32, 64) = 2048 CTAs, 2 per SM
    gemm_mma_kernel<<<grid, THREADS, SMEM_TOTAL>>>(tA, tB, c);
}

// round 16
// speedup vs baseline: 1.0585x; 1.0312x over previous
#include <cuda_runtime.h>
#include <cuda_fp16.h>
#include <cuda.h>
#include <cstdint>

using u32 = uint32_t;

// ---------------- problem dims ----------------
constexpr int Mdim = 8192, Ndim = 4096, KL = 512, RANKS = 8;
constexpr int K4 = RANKS * KL;                 // 4096: plain fp16, 1:1 K packing

// ---------------- GEMM tiling ----------------
constexpr int BM = 128;                        // M per CTA
constexpr int BN = 128;                        // N per CTA
constexpr int BKB = 64;                        // fp16 k per SMEM stage (128B rows)
constexpr int NT = K4 / BKB;                   // 64 k-tiles
constexpr int THREADS = 256;                   // 8 warps: 2(m) x 4(n), warp 64x32

constexpr int A_BYTES = BM * 128;              // 16 KB
constexpr int B_BYTES = BN * 128;              // 16 KB
constexpr int STAGE_BYTES = A_BYTES + B_BYTES; // 32 KB
constexpr int STAGES = 3;
constexpr int CTRL = STAGES * STAGE_BYTES;     // 98304
constexpr int SMEM_TOTAL = CTRL + 64;          // + 6 mbarriers -> 2 CTAs/SM

// ---------------- scratch (device globals = sanctioned scratch) ----------------
__device__ __half g_A2[(size_t)Mdim * K4];   // 67 MB : fl16(a)
__device__ __half g_B2[(size_t)Ndim * K4];   // 33 MB : fl16(b)

// ---------------- PTX helpers ----------------
__device__ __forceinline__ u32 smem_u32(const void* p) {
    u32 r;
    asm("{ .reg .u64 t; cvta.to.shared.u64 t, %1; cvt.u32.u64 %0, t; }"
        : "=r"(r) : "l"(p));
    return r;
}

__device__ __forceinline__ void mbar_init(u32 addr, u32 cnt) {
    asm volatile("mbarrier.init.shared.b64 [%0], %1;" :: "r"(addr), "r"(cnt) : "memory");
}
__device__ __forceinline__ void mbar_expect_tx(u32 addr, u32 bytes) {
    asm volatile("mbarrier.arrive.expect_tx.shared.b64 _, [%0], %1;"
                 :: "r"(addr), "r"(bytes) : "memory");
}
__device__ __forceinline__ void mbar_arrive(u32 addr) {
    asm volatile("mbarrier.arrive.shared.b64 _, [%0];" :: "r"(addr) : "memory");
}
__device__ __forceinline__ void mbar_wait(u32 addr, u32 parity) {
    asm volatile(
        "{\n\t.reg .pred P;\n"
        "WL%=:\n\t"
        "mbarrier.try_wait.parity.acquire.cta.shared::cta.b64 P, [%0], %1, 0x989680;\n\t"
        "@P bra WD%=;\n\t"
        "bra WL%=;\n"
        "WD%=:\n\t}"
        :: "r"(addr), "r"(parity) : "memory");
}

__device__ __forceinline__ void tma2d(u32 smem, const void* tmap, int x, int y, u32 mbar) {
    asm volatile(
        "cp.async.bulk.tensor.2d.shared::cta.global.tile.mbarrier::complete_tx::bytes "
        "[%0], [%1, {%2, %3}], [%4];"
        :: "r"(smem), "l"(tmap), "r"(x), "r"(y), "r"(mbar) : "memory");
}

__device__ __forceinline__ void ldsm_x4(u32& r0, u32& r1, u32& r2, u32& r3, u32 a) {
    asm volatile("ldmatrix.sync.aligned.m8n8.x4.shared.b16 {%0,%1,%2,%3}, [%4];"
                 : "=r"(r0), "=r"(r1), "=r"(r2), "=r"(r3) : "r"(a));
}
__device__ __forceinline__ void hmma_f16(float* c, const u32* a, u32 b0, u32 b1) {
    asm volatile(
        "mma.sync.aligned.m16n8k16.row.col.f32.f16.f16.f32 "
        "{%0,%1,%2,%3}, {%4,%5,%6,%7}, {%8,%9}, {%0,%1,%2,%3};"
        : "+f"(c[0]), "+f"(c[1]), "+f"(c[2]), "+f"(c[3])
        : "r"(a[0]), "r"(a[1]), "r"(a[2]), "r"(a[3]), "r"(b0), "r"(b1));
}

// ---------------- conversion: fp32 -> fp16 (1:1) ----------------
__global__ void __launch_bounds__(256)
convert_kernel(const float* __restrict__ a, const float* __restrict__ b)
{
    constexpr size_t ACH = (size_t)RANKS * Mdim * KL / 8;   // 4,194,304
    constexpr size_t BCH = (size_t)RANKS * Ndim * KL / 8;   // 2,097,152
    size_t id = (size_t)blockIdx.x * 256 + threadIdx.x;
    if (id >= ACH + BCH) return;

    bool isA = id < ACH;
    size_t cid = isA ? id : id - ACH;

    size_t src_row = cid >> 6;            // 64 chunks of 8 floats per (src,row)
    int k0 = (int)(cid & 63) * 8;
    int srk, row;
    if (isA) { srk = (int)(src_row / Mdim); row = (int)(src_row % Mdim); }
    else     { srk = (int)(src_row / Ndim); row = (int)(src_row % Ndim); }

    const float* src = (isA ? a : b) + cid * 8;
    __half* dst = (isA ? g_A2 : g_B2)
        + (size_t)row * K4 + (size_t)(srk * KL + k0);

    float4 f0 = ((const float4*)src)[0];
    float4 f1 = ((const float4*)src)[1];
    float xs[8] = {f0.x, f0.y, f0.z, f0.w, f1.x, f1.y, f1.z, f1.w};

    __align__(16) __half ov[8];
#pragma unroll
    for (int i = 0; i < 8; i++) ov[i] = __float2half_rn(xs[i]);
    *(uint4*)dst = *(const uint4*)ov;
}

// ---------------- HMMA GEMM with TMA + mbarrier pipeline ----------------
__global__ void __launch_bounds__(THREADS, 2)
gemm_mma_kernel(const __grid_constant__ CUtensorMap tmA,
                const __grid_constant__ CUtensorMap tmB,
                float* __restrict__ C)
{
    extern __shared__ __align__(1024) char smem[];
    const u32 sbase = smem_u32(smem);
    const int tid = threadIdx.x;
    const int lane = tid & 31;
    const int w = tid >> 5;            // 8 warps
    const int wm = w >> 2;             // 0..1 : warp row (64 M each)
    const int wn = w & 3;              // 0..3 : warp col (32 N each)

    const int m0 = blockIdx.y * BM;
    const int n0 = blockIdx.x * BN;

    const u32 mb_full = sbase + CTRL;          // 3 x u64
    const u32 mb_empty = sbase + CTRL + 24;    // 3 x u64

    if (tid == 0) {
#pragma unroll
        for (int s = 0; s < 3; s++) {
            mbar_init(mb_full + s * 8, 1);
            mbar_init(mb_empty + s * 8, 8);    // one arrive per warp
        }
    }
    __syncthreads();
    asm volatile("fence.proxy.async.shared::cta;" ::: "memory");

    // ---- prologue: TMA tiles 0,1 into stages 0,1 ----
    if (tid == 0) {
#pragma unroll
        for (int p = 0; p < 2; p++) {
            mbar_expect_tx(mb_full + p * 8, STAGE_BYTES);
            tma2d(sbase + p * STAGE_BYTES,           &tmA, p * BKB, m0, mb_full + p * 8);
            tma2d(sbase + p * STAGE_BYTES + A_BYTES, &tmB, p * BKB, n0, mb_full + p * 8);
        }
    }

    // ---- ldmatrix address precomputation ----
    const u32 frag_xor = (u32)(lane & 7) * 16;
    const u32 khalf = (u32)((lane >> 4) & 1) * 16;
    const int frag_row = (((lane >> 3) & 1) << 3) + (lane & 7);
    u32 aPre[4];
#pragma unroll
    for (int mb = 0; mb < 4; mb++)
        aPre[mb] = (u32)(wm * 64 + mb * 16 + frag_row) * 128;
    u32 bPre[2];
#pragma unroll
    for (int nb = 0; nb < 2; nb++)
        bPre[nb] = (u32)(wn * 32 + nb * 16 + frag_row) * 128;

    float acc[4][4][4];
#pragma unroll
    for (int i = 0; i < 4; i++)
#pragma unroll
        for (int j = 0; j < 4; j++)
#pragma unroll
            for (int q = 0; q < 4; q++) acc[i][j][q] = 0.f;

    u32 af[2][4][4];
    u32 bf[2][2][4];

    auto ldsm_all = [&](int buf, u32 sA_, u32 sB_, u32 kbyte) {
        const u32 kk = (kbyte + khalf) ^ frag_xor;
#pragma unroll
        for (int mb = 0; mb < 4; mb++)
            ldsm_x4(af[buf][mb][0], af[buf][mb][1], af[buf][mb][2], af[buf][mb][3],
                    sA_ + aPre[mb] + kk);
#pragma unroll
        for (int nb = 0; nb < 2; nb++)
            ldsm_x4(bf[buf][nb][0], bf[buf][nb][1], bf[buf][nb][2], bf[buf][nb][3],
                    sB_ + bPre[nb] + kk);
    };
    auto hmma_all = [&](int buf) {
#pragma unroll
        for (int mb = 0; mb < 4; mb++)
#pragma unroll
            for (int nb = 0; nb < 2; nb++) {
                hmma_f16(acc[mb][2 * nb + 0], af[buf][mb], bf[buf][nb][0], bf[buf][nb][2]);
                hmma_f16(acc[mb][2 * nb + 1], af[buf][mb], bf[buf][nb][1], bf[buf][nb][3]);
            }
    };

    // ---- steady-state entry: tile 0 ks0 fragments resident before the loop ----
    mbar_wait(mb_full + 0, 0);
    ldsm_all(0, sbase, sbase + A_BYTES, 0);

    // ---- main loop ----
    // Tile t body: [ks0 frags already in buf0]
    //   producer: TMA tile t+2
    //   ldsm ks1; HMMA ks0 | ldsm ks2; HMMA ks1 | ldsm ks3; HMMA ks2
    //   per-warp arrive empty(stage)            (stage reads done)
    //   HMMA ks3 (issued) ; wait full(t+1) ; ldsm(t+1, ks0)  -> next tile opens hot
    int stage = 0, fpar = 0, epar = 0;
    for (int t = 0; t < NT; t++) {
        int s2 = stage + 2; if (s2 >= 3) s2 -= 3;
        if (t + 2 < NT) {
            if (tid == 0) {
                if (t + 2 >= 3) mbar_wait(mb_empty + s2 * 8, (u32)epar);
                mbar_expect_tx(mb_full + s2 * 8, STAGE_BYTES);
                tma2d(sbase + s2 * STAGE_BYTES,           &tmA, (t + 2) * BKB, m0,
                      mb_full + s2 * 8);
                tma2d(sbase + s2 * STAGE_BYTES + A_BYTES, &tmB, (t + 2) * BKB, n0,
                      mb_full + s2 * 8);
            }
            if (t + 2 >= 3 && s2 == 2) epar ^= 1;
        }

        const u32 sA = sbase + stage * STAGE_BYTES;
        const u32 sB = sA + A_BYTES;

        ldsm_all(1, sA, sB, 32);   hmma_all(0);
        ldsm_all(0, sA, sB, 64);   hmma_all(1);
        ldsm_all(1, sA, sB, 96);   hmma_all(0);

        // all reads of this stage are issued; release it (one arrive per warp)
        __syncwarp();
        if (lane == 0) mbar_arrive(mb_empty + stage * 8);

        hmma_all(1);               // ks3 HMMAs queued into the tensor pipe

        if (t + 1 < NT) {          // overlap next-tile wait+ldsm with ks3 drain
            int ns = stage + 1; if (ns >= 3) ns -= 3;
            const u32 npar = (stage == 2) ? (u32)(fpar ^ 1) : (u32)fpar;
            mbar_wait(mb_full + ns * 8, npar);
            const u32 nA = sbase + ns * STAGE_BYTES;
            ldsm_all(0, nA, nA + A_BYTES, 0);
        }

        if (++stage == 3) { stage = 0; fpar ^= 1; }
    }

    // ---- epilogue ----
    const int er = lane >> 2;
    const int ec = (lane & 3) * 2;
#pragma unroll
    for (int mb = 0; mb < 4; mb++) {
#pragma unroll
        for (int nb = 0; nb < 4; nb++) {
            float* base = C + (size_t)(m0 + wm * 64 + mb * 16 + er) * Ndim
                            + (n0 + wn * 32 + nb * 8 + ec);
            *(float2*)base = make_float2(acc[mb][nb][0], acc[mb][nb][1]);
            *(float2*)(base + (size_t)8 * Ndim) = make_float2(acc[mb][nb][2], acc[mb][nb][3]);
        }
    }
}

// ---------------- launch ----------------
typedef CUresult (*tmap_encode_fn)(
    CUtensorMap*, CUtensorMapDataType, cuuint32_t, void*,
    const cuuint64_t*, const cuuint64_t*, const cuuint32_t*, const cuuint32_t*,
    CUtensorMapInterleave, CUtensorMapSwizzle, CUtensorMapL2promotion,
    CUtensorMapFloatOOBfill);

extern "C" void kernel_launch(void* const* d_in, const int* in_sizes, int n_in,
                              void* d_out, int out_size)
{
    const float* a = (const float*)d_in[0];   // [8, 8192, 512] fp32
    const float* b = (const float*)d_in[1];   // [8, 4096, 512] fp32
    float* c = (float*)d_out;                 // [8192, 4096] fp32

    constexpr size_t TOTAL_CHUNKS =
        ((size_t)RANKS * Mdim * KL + (size_t)RANKS * Ndim * KL) / 8;  // 6,291,456
    convert_kernel<<<(unsigned)(TOTAL_CHUNKS / 256), 256>>>(a, b);

    // Build tensormaps (host-side, deterministic, no allocation)
    void* pa = nullptr; void* pb = nullptr;
    cudaGetSymbolAddress(&pa, g_A2);
    cudaGetSymbolAddress(&pb, g_B2);

    void* fn = nullptr;
    cudaDriverEntryPointQueryResult qr;
    cudaGetDriverEntryPointByVersion("cuTensorMapEncodeTiled", &fn, 12000,
                                     cudaEnableDefault, &qr);
    tmap_encode_fn enc = (tmap_encode_fn)fn;

    CUtensorMap tA, tB;
    cuuint64_t dimsA[2] = {(cuuint64_t)K4, (cuuint64_t)Mdim};
    cuuint64_t dimsB[2] = {(cuuint64_t)K4, (cuuint64_t)Ndim};
    cuuint64_t strides[1] = {(cuuint64_t)K4 * 2};
    cuuint32_t box[2] = {(cuuint32_t)BKB, (cuuint32_t)BM};   // 64 x 128 (=128B x 128 rows)
    cuuint32_t es[2] = {1, 1};
    enc(&tA, CU_TENSOR_MAP_DATA_TYPE_FLOAT16, 2, pa, dimsA, strides, box, es,
        CU_TENSOR_MAP_INTERLEAVE_NONE, CU_TENSOR_MAP_SWIZZLE_128B,
        CU_TENSOR_MAP_L2_PROMOTION_L2_128B, CU_TENSOR_MAP_FLOAT_OOB_FILL_NONE);
    enc(&tB, CU_TENSOR_MAP_DATA_TYPE_FLOAT16, 2, pb, dimsB, strides, box, es,
        CU_TENSOR_MAP_INTERLEAVE_NONE, CU_TENSOR_MAP_SWIZZLE_128B,
        CU_TENSOR_MAP_L2_PROMOTION_L2_128B, CU_TENSOR_MAP_FLOAT_OOB_FILL_NONE);

    cudaFuncSetAttribute(gemm_mma_kernel,
                         cudaFuncAttributeMaxDynamicSharedMemorySize, SMEM_TOTAL);
    dim3 grid(Ndim / BN, Mdim / BM);          // (32, 64) = 2048 CTAs, 2 per SM
    gemm_mma_kernel<<<grid, THREADS, SMEM_TOTAL>>>(tA, tB, c);
}